// round 6
// baseline (speedup 1.0000x reference)
#include <cuda_runtime.h>
#include <math.h>

#define SEQ   2048
#define BATCH 64
#define DIN   512
#define DH    512

typedef unsigned long long u64;

// ---------------- f32x2 packed helpers ----------------
__device__ __forceinline__ u64 dupf(float x) {
    u64 d; asm("mov.b64 %0, {%1, %1};" : "=l"(d) : "f"(x)); return d;
}
__device__ __forceinline__ void fma2(u64& acc, u64 a, u64 b) {
    asm("fma.rn.f32x2 %0, %1, %2, %0;" : "+l"(acc) : "l"(a), "l"(b));
}
__device__ __forceinline__ float2 unpack2(u64 v) {
    float lo, hi;
    asm("mov.b64 {%0, %1}, %2;" : "=f"(lo), "=f"(hi) : "l"(v));
    return make_float2(lo, hi);
}

// ---------------- XLA fast tanh: clamp 7.99881172180175781, passthrough ----------------
__device__ __forceinline__ float xla_tanh(float x) {
    const float kClamp = 7.99881172180175781f;
    float ax = fabsf(x);
    float xc = fminf(fmaxf(x, -kClamp), kClamp);
    float x2 = xc * xc;
    float p = __fmaf_rn(x2, -2.76076847742355e-16f, 2.00018790482477e-13f);
    p = __fmaf_rn(x2, p, -8.60467152213735e-11f);
    p = __fmaf_rn(x2, p, 5.12229709037114e-08f);
    p = __fmaf_rn(x2, p, 1.48572235717979e-05f);
    p = __fmaf_rn(x2, p, 6.37261928875436e-04f);
    p = __fmaf_rn(x2, p, 4.89352455891786e-03f);
    p = xc * p;
    float q = __fmaf_rn(x2, 1.19825839466702e-06f, 1.18534705686654e-04f);
    q = __fmaf_rn(x2, q, 2.26843463243900e-03f);
    q = __fmaf_rn(x2, q, 4.89352518554385e-03f);
    float r = __fdiv_rn(p, q);
    return (ax < 0.0004f) ? x : r;
}

// ---------------- per-batch-group barrier (16 CTAs each, 8 groups) ----------------
__device__ unsigned g_cnt[8 * 32];
__device__ volatile unsigned g_gen[8 * 32];

__device__ __forceinline__ void bg_barrier(int bg) {
    __syncthreads();
    if (threadIdx.x == 0) {
        unsigned gen = g_gen[bg * 32];
        __threadfence();
        if (atomicAdd(&g_cnt[bg * 32], 1u) == 15u) {
            g_cnt[bg * 32] = 0;
            __threadfence();
            g_gen[bg * 32] = gen + 1u;
        } else {
            while (g_gen[bg * 32] == gen) { }
        }
        __threadfence();
    }
    __syncthreads();
}

// ---------------- Kernel 1: xi = x @ W_i2h^T + b_i2h (f32x2 packed) ----------------
// Per element: single fp32 acc (one lane of a packed pair), ascending-k
// fma.rn.f32x2 chain from 0, then one bias add. Bit-identical to scalar FFMA.
#define BM 64
#define BN 64
#define BK 16

__global__ void __launch_bounds__(256) i2h_gemm_kernel(
    const float* __restrict__ A, const float* __restrict__ Bw,
    const float* __restrict__ bias, float* __restrict__ C)
{
    __shared__ float As[BK][BM + 4];
    __shared__ float Bs[BK][BN + 4];
    const int bm = blockIdx.x, bn = blockIdx.y, tid = threadIdx.x;
    const int tm = (tid / 16) * 4, tn = (tid % 16) * 4;
    const int lr = tid / 4, lk = (tid % 4) * 4;
    const float* Aptr = A + ((size_t)bm * BM + lr) * DIN + lk;
    const float* Bptr = Bw + ((size_t)bn * BN + lr) * DIN + lk;

    u64 acc2[4][2];
    #pragma unroll
    for (int i = 0; i < 4; i++) { acc2[i][0] = 0ull; acc2[i][1] = 0ull; }

    for (int k0 = 0; k0 < DIN; k0 += BK) {
        float4 av = *(const float4*)(Aptr + k0);
        float4 bv = *(const float4*)(Bptr + k0);
        As[lk + 0][lr] = av.x; As[lk + 1][lr] = av.y;
        As[lk + 2][lr] = av.z; As[lk + 3][lr] = av.w;
        Bs[lk + 0][lr] = bv.x; Bs[lk + 1][lr] = bv.y;
        Bs[lk + 2][lr] = bv.z; Bs[lk + 3][lr] = bv.w;
        __syncthreads();
        #pragma unroll
        for (int k = 0; k < BK; k++) {
            float4 a4 = *(const float4*)&As[k][tm];
            u64 b01 = *(const u64*)&Bs[k][tn];
            u64 b23 = *(const u64*)&Bs[k][tn + 2];
            float am[4] = {a4.x, a4.y, a4.z, a4.w};
            #pragma unroll
            for (int i = 0; i < 4; i++) {
                u64 ad = dupf(am[i]);
                fma2(acc2[i][0], ad, b01);
                fma2(acc2[i][1], ad, b23);
            }
        }
        __syncthreads();
    }

    const float b0 = bias[bn * BN + tn + 0];
    const float b1 = bias[bn * BN + tn + 1];
    const float b2 = bias[bn * BN + tn + 2];
    const float b3 = bias[bn * BN + tn + 3];
    #pragma unroll
    for (int i = 0; i < 4; i++) {
        float2 p0 = unpack2(acc2[i][0]);
        float2 p1 = unpack2(acc2[i][1]);
        float4 o;
        o.x = p0.x + b0;
        o.y = p0.y + b1;
        o.z = p1.x + b2;
        o.w = p1.y + b3;
        *(float4*)&C[((size_t)bm * BM + tm + i) * DH + bn * BN + tn] = o;
    }
}

// ---------------- Kernel 2: persistent scan (proven bit-exact recipe) ----------------
// 128 CTAs = bg(8 x 8 rows) x cg(16 x 32 cols). 128 threads/CTA.
// Warp w handles rows {2w, 2w+1}; lane = column. Per output element:
// ONE sequential ascending-k fp32 FMA chain (init 0) -> (xi+dot)+b -> xla_tanh.
#define WSTRIDE 516

__global__ void __launch_bounds__(128, 1) rnn_scan_kernel(
    const float* __restrict__ h0, const float* __restrict__ W_h2h,
    const float* __restrict__ b_h2h, float* __restrict__ out,
    float* __restrict__ h_last)
{
    extern __shared__ float sm[];
    float* W_s = sm;                      // [32][WSTRIDE]
    float* h_s = sm + 32 * WSTRIDE;       // [8][512]

    const int cg = blockIdx.x & 15;
    const int bg = blockIdx.x >> 4;
    const int c0 = cg * 32;
    const int b0 = bg * 8;
    const int tid = threadIdx.x;
    const int lane = tid & 31;
    const int w = tid >> 5;
    const int rA = 2 * w, rB = 2 * w + 1;
    const int col = c0 + lane;

    for (int idx = tid; idx < 32 * 512; idx += 128) {
        int c = idx >> 9, k = idx & 511;
        W_s[c * WSTRIDE + k] = W_h2h[(size_t)(c0 + c) * DH + k];
    }
    const float bias = b_h2h[col];
    const float4* Wp  = (const float4*)&W_s[lane * WSTRIDE];
    const float4* hA4 = (const float4*)&h_s[rA * 512];
    const float4* hB4 = (const float4*)&h_s[rB * 512];
    __syncthreads();

    for (int t = 0; t < SEQ; t++) {
        const float4* hsrc = (const float4*)((t == 0)
            ? (h0 + (size_t)b0 * DH)
            : (out + ((size_t)(t - 1) * BATCH + b0) * DH));
        float4* hd = (float4*)h_s;
        #pragma unroll
        for (int j = 0; j < 8; j++)
            hd[tid + 128 * j] = hsrc[tid + 128 * j];

        const size_t oA = ((size_t)t * BATCH + b0 + rA) * DH + col;
        const size_t oB = ((size_t)t * BATCH + b0 + rB) * DH + col;
        float xiA = out[oA];
        float xiB = out[oB];
        __syncthreads();

        float a0 = 0.f, a1 = 0.f;
        #pragma unroll 8
        for (int k4 = 0; k4 < 128; k4++) {
            float4 wv = Wp[k4];
            float4 ha = hA4[k4];
            float4 hb = hB4[k4];
            a0 = __fmaf_rn(ha.x, wv.x, a0);
            a0 = __fmaf_rn(ha.y, wv.y, a0);
            a0 = __fmaf_rn(ha.z, wv.z, a0);
            a0 = __fmaf_rn(ha.w, wv.w, a0);
            a1 = __fmaf_rn(hb.x, wv.x, a1);
            a1 = __fmaf_rn(hb.y, wv.y, a1);
            a1 = __fmaf_rn(hb.z, wv.z, a1);
            a1 = __fmaf_rn(hb.w, wv.w, a1);
        }

        float vA = xla_tanh((xiA + a0) + bias);
        float vB = xla_tanh((xiB + a1) + bias);
        out[oA] = vA;
        out[oB] = vB;
        if (t == SEQ - 1 && h_last) {
            h_last[(size_t)(b0 + rA) * DH + col] = vA;
            h_last[(size_t)(b0 + rB) * DH + col] = vB;
        }
        bg_barrier(bg);
    }
}

// ---------------- launch ----------------
extern "C" void kernel_launch(void* const* d_in, const int* in_sizes, int n_in,
                              void* d_out, int out_size) {
    const float* x     = (const float*)d_in[0];
    const float* h0    = (const float*)d_in[1];
    const float* W_i2h = (const float*)d_in[2];
    const float* b_i2h = (const float*)d_in[3];
    const float* W_h2h = (const float*)d_in[4];
    const float* b_h2h = (const float*)d_in[5];
    float* out = (float*)d_out;

    float* h_last = nullptr;
    if ((long long)out_size >= (long long)(SEQ + 1) * BATCH * DH)
        h_last = out + (size_t)SEQ * BATCH * DH;

    dim3 g1(SEQ * BATCH / BM, DH / BN);
    i2h_gemm_kernel<<<g1, 256>>>(x, W_i2h, b_i2h, out);

    const int smem = (32 * WSTRIDE + 8 * 512) * sizeof(float);
    cudaFuncSetAttribute(rnn_scan_kernel,
                         cudaFuncAttributeMaxDynamicSharedMemorySize, smem);
    rnn_scan_kernel<<<128, 128, smem>>>(h0, W_h2h, b_h2h, out, h_last);
}